// round 15
// baseline (speedup 1.0000x reference)
#include <cuda_runtime.h>
#include <cuda_bf16.h>
#include <cuda_fp16.h>
#include <math.h>

#define N_NODES 40000
#define E_EDGES 1280000
#define S_DIM 64
#define V_DIM 16
#define R_DIM 32

#define TBINS 4096
#define PK_ROWS 4097
#define PK_COLS 320          // halfs per row -> 640 bytes/row

#define SRROW 176            // g_SrcRow floats per node (704 B)

// Per-node data
__device__ __align__(16) float g_Pa[N_NODES * S_DIM];
__device__ __align__(16) float g_SrcRow[N_NODES * SRROW];  // [Pb|scalars interleaved | vectors(48)]
// Distance table (packed fp16 val/slope)
__device__ __align__(16) __half g_tabh[PK_ROWS * PK_COLS];

__device__ __forceinline__ float silu_f(float x) {
    return x / (1.0f + __expf(-x));
}
__device__ __forceinline__ void red_add_v4(float* ptr, float a, float b, float c, float d) {
    asm volatile("red.global.v4.f32.add [%0], {%1, %2, %3, %4};"
                 :: "l"(ptr), "f"(a), "f"(b), "f"(c), "f"(d) : "memory");
}

// ---------------------------------------------------------------------------
__global__ void init_out_kernel(const float* __restrict__ scalars,
                                const float* __restrict__ vectors,
                                float* __restrict__ out) {
    const int NS4 = (N_NODES * S_DIM) / 4;
    const int NV4 = (N_NODES * V_DIM * 3) / 4;
    int i = blockIdx.x * blockDim.x + threadIdx.x;
    if (i < NS4) {
        reinterpret_cast<float4*>(out)[i] =
            reinterpret_cast<const float4*>(scalars)[i];
    } else if (i < NS4 + NV4) {
        reinterpret_cast<float4*>(out)[i] =
            reinterpret_cast<const float4*>(vectors)[i - NS4];
    }
}

// ---------------------------------------------------------------------------
// proj: Pa = ba1 + s@Wa1[0:64]; SrcRow = [Pb|scalars interleaved | vectors]
// ---------------------------------------------------------------------------
#define PROJ_NB 32
__global__ __launch_bounds__(256) void proj_kernel(
    const float* __restrict__ scalars,
    const float* __restrict__ vectors,
    const float* __restrict__ Wa1,
    const float* __restrict__ ba1) {
    __shared__ __align__(16) float sWi[64 * 128];
    __shared__ __align__(16) float sS[PROJ_NB * 64];

    const int tid = threadIdx.x;
    const int n0 = blockIdx.x * PROJ_NB;

    for (int idx = tid; idx < 64 * 128; idx += 256) {
        int k = idx >> 7, r = idx & 127, j = r >> 1, h = r & 1;
        sWi[idx] = Wa1[(h * 64 + k) * 64 + j];
    }
    for (int i = tid; i < PROJ_NB * 64; i += 256) sS[i] = scalars[n0 * 64 + i];
    __syncthreads();

    const int j = tid & 63;
    const int grp = tid >> 6;
    const float* sbase = &sS[grp * 8 * 64];

    float pa[8], pb[8];
    {
        const float b = __ldg(&ba1[j]);
#pragma unroll
        for (int nn = 0; nn < 8; nn++) { pa[nn] = b; pb[nn] = 0.0f; }
    }

#pragma unroll 4
    for (int k = 0; k < 64; k++) {
        float2 w = *reinterpret_cast<const float2*>(&sWi[k * 128 + 2 * j]);
#pragma unroll
        for (int nn = 0; nn < 8; nn++) {
            float s = sbase[nn * 64 + k];
            pa[nn] = fmaf(s, w.x, pa[nn]);
            pb[nn] = fmaf(s, w.y, pb[nn]);
        }
    }

#pragma unroll
    for (int nn = 0; nn < 8; nn++) {
        const int node = n0 + grp * 8 + nn;
        g_Pa[node * 64 + j] = pa[nn];
        int base = node * SRROW + (j >> 1) * 4 + (j & 1);
        g_SrcRow[base] = pb[nn];
        g_SrcRow[base + 2] = sbase[nn * 64 + j];
        if (j < 48)
            g_SrcRow[node * SRROW + 128 + j] = __ldg(&vectors[node * 48 + j]);
    }
}

// ---------------------------------------------------------------------------
// merged table+pack (unchanged from R14)
// ---------------------------------------------------------------------------
__global__ __launch_bounds__(320) void tablepack_kernel(
    const float* __restrict__ W1, const float* __restrict__ b1,
    const float* __restrict__ W2, const float* __restrict__ b2,
    const float* __restrict__ Wa1) {
    __shared__ float rbf[2][32];
    __shared__ float hh[2][32];
    __shared__ float raw[2][160];

    const int t = threadIdx.x;
    const int hf = (t >= 160) ? 1 : 0;
    const int c = hf ? (t - 160) : t;
    const int row = blockIdx.x + hf;
    const float d = fminf((float)row, (float)TBINS) * (10.0f / TBINS);

    if (c < 32) {
        float freq01 = 0.1f * (float)(c + 1);
        float ds = fmaxf(d, 1e-8f);
        float bess;
        if (d < 1e-6f) bess = (float)M_PI * freq01;
        else           bess = sinpif(d * freq01) / ds;
        float cut = (d < 10.0f) ? 0.5f * (cospif(d * 0.1f) + 1.0f) : 0.0f;
        rbf[hf][c] = bess * cut;
    }
    __syncthreads();
    if (c < 32) {
        float acc = b1[c];
#pragma unroll 8
        for (int k = 0; k < 32; k++) acc = fmaf(rbf[hf][k], W1[k * 32 + c], acc);
        hh[hf][c] = silu_f(acc);
    }
    __syncthreads();

    float outv;
    if (c < 64) {
        float acc = b2[c];
#pragma unroll 8
        for (int jj = 0; jj < 32; jj++) acc = fmaf(hh[hf][jj], W2[jj * 96 + c], acc);
        outv = acc;
    } else if (c < 128) {
        int cc = c - 64;
        float acc = 0.0f;
#pragma unroll 8
        for (int k = 0; k < 32; k++) acc = fmaf(rbf[hf][k], Wa1[(128 + k) * 64 + cc], acc);
        outv = acc;
    } else {
        int cc = 64 + c - 128;
        float acc = b2[cc];
#pragma unroll 8
        for (int jj = 0; jj < 32; jj++) acc = fmaf(hh[hf][jj], W2[jj * 96 + cc], acc);
        outv = acc;
    }
    raw[hf][c] = outv;
    __syncthreads();

    const float* r0 = raw[0];
    const float* r1 = raw[1];
    float v;
    if (t < 128) {
        int g = t >> 3, k = t & 7;
        int col = 4 * g + (k & 3);
        v = (k < 4) ? r0[col] : (r1[col] - r0[col]);
    } else if (t < 256) {
        int u = t - 128;
        int g = u >> 3, k = u & 7;
        int col = 64 + 4 * g + (k & 3);
        v = (k < 4) ? r0[col] : (r1[col] - r0[col]);
    } else {
        int u = t - 256;
        int vg = u >> 2, k = u & 3;
        int col = 128 + vg + ((k >= 2) ? 16 : 0);
        v = ((k & 1) == 0) ? r0[col] : (r1[col] - r0[col]);
    }
    g_tabh[blockIdx.x * PK_COLS + t] = __float2half(v);
}

// ---------------------------------------------------------------------------
// edge kernel: same as R13/R14 winner but register-capped for 5 blocks/SM.
// ---------------------------------------------------------------------------
__global__ __launch_bounds__(256, 5) void edge_kernel(
    const float* __restrict__ edge_vec,
    const int* __restrict__ ei,
    const float* __restrict__ Wa2,
    const float* __restrict__ ba2,
    float* __restrict__ out) {

    __shared__ __align__(16) float sParam[8][32][8];   // 8 KB

    const int tid = threadIdx.x;
    const int warp = tid >> 5;
    const int lane = tid & 31;
    const int half = lane >> 4;
    const int l = lane & 15;

    const float ba2v = __ldg(&ba2[0]);
    const float4 wq = *reinterpret_cast<const float4*>(Wa2 + 4 * l);

    const char* tabBase = (const char*)g_tabh;
    const char* paBase = (const char*)g_Pa;
    const char* srBase = (const char*)g_SrcRow;
    char* outSBase = (char*)out;
    char* outVBase = (char*)(out + N_NODES * S_DIM);

    const unsigned lA = (unsigned)l * 16u;

    const int e0i = 4 * l;
    const int v0 = e0i / 3;
    const int v1 = (e0i + 3) / 3;
    const int cmp0 = e0i % 3, cmp1 = (e0i + 1) % 3,
              cmp2 = (e0i + 2) % 3, cmp3 = (e0i + 3) % 3;
    const bool sk1 = ((e0i + 1) / 3) != v0;
    const bool sk2 = ((e0i + 2) / 3) != v0;
    const bool sk3 = ((e0i + 3) / 3) != v0;

    const int NWT = E_EDGES / 32;

    for (int wt = blockIdx.x * 8 + warp; wt < NWT; wt += gridDim.x * 8) {
        const int e = wt * 32 + lane;

        // ---- Phase A ----
        float x = __ldg(&edge_vec[3 * e + 0]);
        float y = __ldg(&edge_vec[3 * e + 1]);
        float z = __ldg(&edge_vec[3 * e + 2]);
        int sL = __ldg(&ei[e]);
        int dL = __ldg(&ei[E_EDGES + e]);
        float d = sqrtf(fmaf(x, x, fmaf(y, y, z * z)));
        float iv = 1.0f / fmaxf(d, 1e-8f);
        float dn = d * ((float)TBINS / 10.0f);
        int bin = min((int)dn, TBINS);

        __syncwarp();
        {
            float4 p0 = make_float4(dn - (float)bin, x * iv, y * iv, z * iv);
            float4 p1;
            p1.x = __uint_as_float((unsigned)bin * 640u);
            p1.y = __uint_as_float((unsigned)dL * 256u);
            p1.z = __uint_as_float((unsigned)sL * (SRROW * 4u));
            p1.w = 0.0f;
            *reinterpret_cast<float4*>(&sParam[warp][lane][0]) = p0;
            *reinterpret_cast<float4*>(&sParam[warp][lane][4]) = p1;
        }
        __syncwarp();

        // ---- Phase B: 16 iterations, 2 edges each ----
#pragma unroll 4
        for (int i = 0; i < 16; i++) {
            const int et = 2 * i + half;
            float4 P0 = *reinterpret_cast<const float4*>(&sParam[warp][et][0]);
            float4 P1 = *reinterpret_cast<const float4*>(&sParam[warp][et][4]);
            float w = P0.x, ux = P0.y, uy = P0.z, uz = P0.w;
            unsigned rowOff = __float_as_uint(P1.x);
            unsigned dstOff = __float_as_uint(P1.y);
            unsigned srcOff = __float_as_uint(P1.z);
            unsigned vdOff = dstOff - (dstOff >> 2);   // dL*192

            uint4 Araw = *reinterpret_cast<const uint4*>(tabBase + rowOff + lA);
            uint4 Braw = *reinterpret_cast<const uint4*>(tabBase + rowOff + 256u + lA);
            float4 Pa = *reinterpret_cast<const float4*>(paBase + dstOff + lA);
            float4 S0 = *reinterpret_cast<const float4*>(srBase + srcOff + l * 32u);
            float4 S1 = *reinterpret_cast<const float4*>(srBase + srcOff + l * 32u + 16u);

            float2 Av0 = __half22float2(*reinterpret_cast<const __half2*>(&Araw.x));
            float2 Av1 = __half22float2(*reinterpret_cast<const __half2*>(&Araw.y));
            float2 As0 = __half22float2(*reinterpret_cast<const __half2*>(&Araw.z));
            float2 As1 = __half22float2(*reinterpret_cast<const __half2*>(&Araw.w));
            float2 Bv0 = __half22float2(*reinterpret_cast<const __half2*>(&Braw.x));
            float2 Bv1 = __half22float2(*reinterpret_cast<const __half2*>(&Braw.y));
            float2 Bs0 = __half22float2(*reinterpret_cast<const __half2*>(&Braw.z));
            float2 Bs1 = __half22float2(*reinterpret_cast<const __half2*>(&Braw.w));

            float f0 = fmaf(w, As0.x, Av0.x);
            float f1 = fmaf(w, As0.y, Av0.y);
            float f2c = fmaf(w, As1.x, Av1.x);
            float f3 = fmaf(w, As1.y, Av1.y);
            float q0 = fmaf(w, Bs0.x, Bv0.x);
            float q1 = fmaf(w, Bs0.y, Bv0.y);
            float q2 = fmaf(w, Bs1.x, Bv1.x);
            float q3 = fmaf(w, Bs1.y, Bv1.y);

            float a0 = Pa.x + S0.x + q0;
            float a1 = Pa.y + S0.y + q1;
            float a2 = Pa.z + S1.x + q2;
            float a3 = Pa.w + S1.y + q3;

            float p = fmaf(silu_f(a0), wq.x,
                      fmaf(silu_f(a1), wq.y,
                      fmaf(silu_f(a2), wq.z, silu_f(a3) * wq.w)));
            p += __shfl_xor_sync(0xffffffffu, p, 8);
            p += __shfl_xor_sync(0xffffffffu, p, 4);
            p += __shfl_xor_sync(0xffffffffu, p, 2);
            p += __shfl_xor_sync(0xffffffffu, p, 1);
            float att = 1.0f / (1.0f + __expf(-(p + ba2v)));

            red_add_v4(reinterpret_cast<float*>(outSBase + dstOff + lA),
                       att * S0.z * f0, att * S0.w * f1,
                       att * S1.z * f2c, att * S1.w * f3);

            if (l < 12) {
                float4 vv = *reinterpret_cast<const float4*>(srBase + srcOff + 512u + lA);
                uint2 C0 = *reinterpret_cast<const uint2*>(tabBase + rowOff + 512u + 8u * v0);
                uint2 C1 = *reinterpret_cast<const uint2*>(tabBase + rowOff + 512u + 8u * v1);
                float2 c0a = __half22float2(*reinterpret_cast<const __half2*>(&C0.x));
                float2 c0b = __half22float2(*reinterpret_cast<const __half2*>(&C0.y));
                float2 c1a = __half22float2(*reinterpret_cast<const __half2*>(&C1.x));
                float2 c1b = __half22float2(*reinterpret_cast<const __half2*>(&C1.y));
                float fv0_ = fmaf(w, c0a.y, c0a.x);
                float fg0_ = fmaf(w, c0b.y, c0b.x);
                float fv1_ = fmaf(w, c1a.y, c1a.x);
                float fg1_ = fmaf(w, c1b.y, c1b.x);

                float vfa = fv0_;
                float vga = fg0_;
                float vfb = sk1 ? fv1_ : fv0_;
                float vgb = sk1 ? fg1_ : fg0_;
                float vfc = sk2 ? fv1_ : fv0_;
                float vgc = sk2 ? fg1_ : fg0_;
                float vfd = sk3 ? fv1_ : fv0_;
                float vgd = sk3 ? fg1_ : fg0_;

                float sha = (cmp0 == 0) ? uy : ((cmp0 == 1) ? uz : ux);
                float shb = (cmp1 == 0) ? uy : ((cmp1 == 1) ? uz : ux);
                float shcx = (cmp2 == 0) ? uy : ((cmp2 == 1) ? uz : ux);
                float shd = (cmp3 == 0) ? uy : ((cmp3 == 1) ? uz : ux);

                float m0 = att * fmaf(vv.x, vfa, vga * sha);
                float m1 = att * fmaf(vv.y, vfb, vgb * shb);
                float m2 = att * fmaf(vv.z, vfc, vgc * shcx);
                float m3 = att * fmaf(vv.w, vfd, vgd * shd);
                red_add_v4(reinterpret_cast<float*>(outVBase + vdOff + lA),
                           m0, m1, m2, m3);
            }
        }
    }
}

// ---------------------------------------------------------------------------
// Fork-join launch: init(s0) || tablepack(s1) || proj(s2), then edge(s0).
// ---------------------------------------------------------------------------
static cudaStream_t g_s1 = nullptr, g_s2 = nullptr;
static cudaEvent_t g_evRoot = nullptr, g_ev1 = nullptr, g_ev2 = nullptr;

extern "C" void kernel_launch(void* const* d_in, const int* in_sizes, int n_in,
                              void* d_out, int out_size) {
    const float* scalars = (const float*)d_in[0];
    const float* vectors = (const float*)d_in[1];
    const float* edge_vec = (const float*)d_in[2];
    const float* W1 = (const float*)d_in[3];
    const float* b1 = (const float*)d_in[4];
    const float* W2 = (const float*)d_in[5];
    const float* b2 = (const float*)d_in[6];
    const float* Wa1 = (const float*)d_in[7];
    const float* ba1 = (const float*)d_in[8];
    const float* Wa2 = (const float*)d_in[9];
    const float* ba2 = (const float*)d_in[10];
    const int* ei = (const int*)d_in[11];
    float* out = (float*)d_out;

    if (g_s1 == nullptr) {
        cudaStreamCreateWithFlags(&g_s1, cudaStreamNonBlocking);
        cudaStreamCreateWithFlags(&g_s2, cudaStreamNonBlocking);
        cudaEventCreateWithFlags(&g_evRoot, cudaEventDisableTiming);
        cudaEventCreateWithFlags(&g_ev1, cudaEventDisableTiming);
        cudaEventCreateWithFlags(&g_ev2, cudaEventDisableTiming);
    }

    // fork
    cudaEventRecord(g_evRoot, 0);
    cudaStreamWaitEvent(g_s1, g_evRoot, 0);
    cudaStreamWaitEvent(g_s2, g_evRoot, 0);

    const int TOT4 = (N_NODES * S_DIM + N_NODES * V_DIM * 3) / 4;
    init_out_kernel<<<(TOT4 + 255) / 256, 256>>>(scalars, vectors, out);
    tablepack_kernel<<<PK_ROWS, 320, 0, g_s1>>>(W1, b1, W2, b2, Wa1);
    proj_kernel<<<N_NODES / PROJ_NB, 256, 0, g_s2>>>(scalars, vectors, Wa1, ba1);

    // join
    cudaEventRecord(g_ev1, g_s1);
    cudaEventRecord(g_ev2, g_s2);
    cudaStreamWaitEvent(0, g_ev1, 0);
    cudaStreamWaitEvent(0, g_ev2, 0);

    edge_kernel<<<2960, 256>>>(edge_vec, ei, Wa2, ba2, out);
}

// round 16
// speedup vs baseline: 1.0645x; 1.0645x over previous
#include <cuda_runtime.h>
#include <cuda_bf16.h>
#include <cuda_fp16.h>
#include <math.h>

#define N_NODES 40000
#define E_EDGES 1280000
#define S_DIM 64
#define V_DIM 16
#define R_DIM 32

#define TBINS 4096
#define PK_ROWS 4097
#define PK_COLS 320          // halfs per row -> 640 bytes/row

#define SRROW 176            // g_SrcRow floats per node (704 B)

// Per-node data
__device__ __align__(16) float g_Pa[N_NODES * S_DIM];
__device__ __align__(16) float g_SrcRow[N_NODES * SRROW];  // [Pb|scalars interleaved | vectors(48)]
// Distance table (packed fp16 val/slope)
__device__ __align__(16) __half g_tabh[PK_ROWS * PK_COLS];

__device__ __forceinline__ float silu_f(float x) {
    return x / (1.0f + __expf(-x));
}
__device__ __forceinline__ void red_add_v4(float* ptr, float a, float b, float c, float d) {
    asm volatile("red.global.v4.f32.add [%0], {%1, %2, %3, %4};"
                 :: "l"(ptr), "f"(a), "f"(b), "f"(c), "f"(d) : "memory");
}

// ---------------------------------------------------------------------------
__global__ void init_out_kernel(const float* __restrict__ scalars,
                                const float* __restrict__ vectors,
                                float* __restrict__ out) {
    const int NS4 = (N_NODES * S_DIM) / 4;
    const int NV4 = (N_NODES * V_DIM * 3) / 4;
    int i = blockIdx.x * blockDim.x + threadIdx.x;
    if (i < NS4) {
        reinterpret_cast<float4*>(out)[i] =
            reinterpret_cast<const float4*>(scalars)[i];
    } else if (i < NS4 + NV4) {
        reinterpret_cast<float4*>(out)[i] =
            reinterpret_cast<const float4*>(vectors)[i - NS4];
    }
}

// ---------------------------------------------------------------------------
// proj: Pa = ba1 + s@Wa1[0:64]; SrcRow = [Pb|scalars interleaved | vectors]
// ---------------------------------------------------------------------------
#define PROJ_NB 32
__global__ __launch_bounds__(256) void proj_kernel(
    const float* __restrict__ scalars,
    const float* __restrict__ vectors,
    const float* __restrict__ Wa1,
    const float* __restrict__ ba1) {
    __shared__ __align__(16) float sWi[64 * 128];
    __shared__ __align__(16) float sS[PROJ_NB * 64];

    const int tid = threadIdx.x;
    const int n0 = blockIdx.x * PROJ_NB;

    for (int idx = tid; idx < 64 * 128; idx += 256) {
        int k = idx >> 7, r = idx & 127, j = r >> 1, h = r & 1;
        sWi[idx] = Wa1[(h * 64 + k) * 64 + j];
    }
    for (int i = tid; i < PROJ_NB * 64; i += 256) sS[i] = scalars[n0 * 64 + i];
    __syncthreads();

    const int j = tid & 63;
    const int grp = tid >> 6;
    const float* sbase = &sS[grp * 8 * 64];

    float pa[8], pb[8];
    {
        const float b = __ldg(&ba1[j]);
#pragma unroll
        for (int nn = 0; nn < 8; nn++) { pa[nn] = b; pb[nn] = 0.0f; }
    }

#pragma unroll 4
    for (int k = 0; k < 64; k++) {
        float2 w = *reinterpret_cast<const float2*>(&sWi[k * 128 + 2 * j]);
#pragma unroll
        for (int nn = 0; nn < 8; nn++) {
            float s = sbase[nn * 64 + k];
            pa[nn] = fmaf(s, w.x, pa[nn]);
            pb[nn] = fmaf(s, w.y, pb[nn]);
        }
    }

#pragma unroll
    for (int nn = 0; nn < 8; nn++) {
        const int node = n0 + grp * 8 + nn;
        g_Pa[node * 64 + j] = pa[nn];
        int base = node * SRROW + (j >> 1) * 4 + (j & 1);
        g_SrcRow[base] = pb[nn];
        g_SrcRow[base + 2] = sbase[nn * 64 + j];
        if (j < 48)
            g_SrcRow[node * SRROW + 128 + j] = __ldg(&vectors[node * 48 + j]);
    }
}

// ---------------------------------------------------------------------------
// merged table+pack
// ---------------------------------------------------------------------------
__global__ __launch_bounds__(320) void tablepack_kernel(
    const float* __restrict__ W1, const float* __restrict__ b1,
    const float* __restrict__ W2, const float* __restrict__ b2,
    const float* __restrict__ Wa1) {
    __shared__ float rbf[2][32];
    __shared__ float hh[2][32];
    __shared__ float raw[2][160];

    const int t = threadIdx.x;
    const int hf = (t >= 160) ? 1 : 0;
    const int c = hf ? (t - 160) : t;
    const int row = blockIdx.x + hf;
    const float d = fminf((float)row, (float)TBINS) * (10.0f / TBINS);

    if (c < 32) {
        float freq01 = 0.1f * (float)(c + 1);
        float ds = fmaxf(d, 1e-8f);
        float bess;
        if (d < 1e-6f) bess = (float)M_PI * freq01;
        else           bess = sinpif(d * freq01) / ds;
        float cut = (d < 10.0f) ? 0.5f * (cospif(d * 0.1f) + 1.0f) : 0.0f;
        rbf[hf][c] = bess * cut;
    }
    __syncthreads();
    if (c < 32) {
        float acc = b1[c];
#pragma unroll 8
        for (int k = 0; k < 32; k++) acc = fmaf(rbf[hf][k], W1[k * 32 + c], acc);
        hh[hf][c] = silu_f(acc);
    }
    __syncthreads();

    float outv;
    if (c < 64) {
        float acc = b2[c];
#pragma unroll 8
        for (int jj = 0; jj < 32; jj++) acc = fmaf(hh[hf][jj], W2[jj * 96 + c], acc);
        outv = acc;
    } else if (c < 128) {
        int cc = c - 64;
        float acc = 0.0f;
#pragma unroll 8
        for (int k = 0; k < 32; k++) acc = fmaf(rbf[hf][k], Wa1[(128 + k) * 64 + cc], acc);
        outv = acc;
    } else {
        int cc = 64 + c - 128;
        float acc = b2[cc];
#pragma unroll 8
        for (int jj = 0; jj < 32; jj++) acc = fmaf(hh[hf][jj], W2[jj * 96 + cc], acc);
        outv = acc;
    }
    raw[hf][c] = outv;
    __syncthreads();

    const float* r0 = raw[0];
    const float* r1 = raw[1];
    float v;
    if (t < 128) {
        int g = t >> 3, k = t & 7;
        int col = 4 * g + (k & 3);
        v = (k < 4) ? r0[col] : (r1[col] - r0[col]);
    } else if (t < 256) {
        int u = t - 128;
        int g = u >> 3, k = u & 7;
        int col = 64 + 4 * g + (k & 3);
        v = (k < 4) ? r0[col] : (r1[col] - r0[col]);
    } else {
        int u = t - 256;
        int vg = u >> 2, k = u & 3;
        int col = 128 + vg + ((k >= 2) ? 16 : 0);
        v = ((k & 1) == 0) ? r0[col] : (r1[col] - r0[col]);
    }
    g_tabh[blockIdx.x * PK_COLS + t] = __float2half(v);
}

// ---------------------------------------------------------------------------
// edge kernel: R14 config (no min-blocks cap), node gathers via __ldcg
// so the fp16 table keeps L1 residency.
// ---------------------------------------------------------------------------
__global__ __launch_bounds__(256) void edge_kernel(
    const float* __restrict__ edge_vec,
    const int* __restrict__ ei,
    const float* __restrict__ Wa2,
    const float* __restrict__ ba2,
    float* __restrict__ out) {

    __shared__ __align__(16) float sParam[8][32][8];   // 8 KB

    const int tid = threadIdx.x;
    const int warp = tid >> 5;
    const int lane = tid & 31;
    const int half = lane >> 4;
    const int l = lane & 15;

    const float ba2v = __ldg(&ba2[0]);
    const float4 wq = *reinterpret_cast<const float4*>(Wa2 + 4 * l);

    const char* tabBase = (const char*)g_tabh;
    const char* paBase = (const char*)g_Pa;
    const char* srBase = (const char*)g_SrcRow;
    char* outSBase = (char*)out;
    char* outVBase = (char*)(out + N_NODES * S_DIM);

    const unsigned lA = (unsigned)l * 16u;

    const int e0i = 4 * l;
    const int v0 = e0i / 3;
    const int v1 = (e0i + 3) / 3;
    const int cmp0 = e0i % 3, cmp1 = (e0i + 1) % 3,
              cmp2 = (e0i + 2) % 3, cmp3 = (e0i + 3) % 3;
    const bool sk1 = ((e0i + 1) / 3) != v0;
    const bool sk2 = ((e0i + 2) / 3) != v0;
    const bool sk3 = ((e0i + 3) / 3) != v0;

    const int NWT = E_EDGES / 32;

    for (int wt = blockIdx.x * 8 + warp; wt < NWT; wt += gridDim.x * 8) {
        const int e = wt * 32 + lane;

        // ---- Phase A ----
        float x = __ldg(&edge_vec[3 * e + 0]);
        float y = __ldg(&edge_vec[3 * e + 1]);
        float z = __ldg(&edge_vec[3 * e + 2]);
        int sL = __ldg(&ei[e]);
        int dL = __ldg(&ei[E_EDGES + e]);
        float d = sqrtf(fmaf(x, x, fmaf(y, y, z * z)));
        float iv = 1.0f / fmaxf(d, 1e-8f);
        float dn = d * ((float)TBINS / 10.0f);
        int bin = min((int)dn, TBINS);

        __syncwarp();
        {
            float4 p0 = make_float4(dn - (float)bin, x * iv, y * iv, z * iv);
            float4 p1;
            p1.x = __uint_as_float((unsigned)bin * 640u);
            p1.y = __uint_as_float((unsigned)dL * 256u);
            p1.z = __uint_as_float((unsigned)sL * (SRROW * 4u));
            p1.w = 0.0f;
            *reinterpret_cast<float4*>(&sParam[warp][lane][0]) = p0;
            *reinterpret_cast<float4*>(&sParam[warp][lane][4]) = p1;
        }
        __syncwarp();

        // ---- Phase B: 16 iterations, 2 edges each ----
#pragma unroll 4
        for (int i = 0; i < 16; i++) {
            const int et = 2 * i + half;
            float4 P0 = *reinterpret_cast<const float4*>(&sParam[warp][et][0]);
            float4 P1 = *reinterpret_cast<const float4*>(&sParam[warp][et][4]);
            float w = P0.x, ux = P0.y, uy = P0.z, uz = P0.w;
            unsigned rowOff = __float_as_uint(P1.x);
            unsigned dstOff = __float_as_uint(P1.y);
            unsigned srcOff = __float_as_uint(P1.z);
            unsigned vdOff = dstOff - (dstOff >> 2);   // dL*192

            uint4 Araw = *reinterpret_cast<const uint4*>(tabBase + rowOff + lA);
            uint4 Braw = *reinterpret_cast<const uint4*>(tabBase + rowOff + 256u + lA);
            float4 Pa = __ldcg(reinterpret_cast<const float4*>(paBase + dstOff + lA));
            float4 S0 = __ldcg(reinterpret_cast<const float4*>(srBase + srcOff + l * 32u));
            float4 S1 = __ldcg(reinterpret_cast<const float4*>(srBase + srcOff + l * 32u + 16u));

            float2 Av0 = __half22float2(*reinterpret_cast<const __half2*>(&Araw.x));
            float2 Av1 = __half22float2(*reinterpret_cast<const __half2*>(&Araw.y));
            float2 As0 = __half22float2(*reinterpret_cast<const __half2*>(&Araw.z));
            float2 As1 = __half22float2(*reinterpret_cast<const __half2*>(&Araw.w));
            float2 Bv0 = __half22float2(*reinterpret_cast<const __half2*>(&Braw.x));
            float2 Bv1 = __half22float2(*reinterpret_cast<const __half2*>(&Braw.y));
            float2 Bs0 = __half22float2(*reinterpret_cast<const __half2*>(&Braw.z));
            float2 Bs1 = __half22float2(*reinterpret_cast<const __half2*>(&Braw.w));

            float f0 = fmaf(w, As0.x, Av0.x);
            float f1 = fmaf(w, As0.y, Av0.y);
            float f2c = fmaf(w, As1.x, Av1.x);
            float f3 = fmaf(w, As1.y, Av1.y);
            float q0 = fmaf(w, Bs0.x, Bv0.x);
            float q1 = fmaf(w, Bs0.y, Bv0.y);
            float q2 = fmaf(w, Bs1.x, Bv1.x);
            float q3 = fmaf(w, Bs1.y, Bv1.y);

            float a0 = Pa.x + S0.x + q0;
            float a1 = Pa.y + S0.y + q1;
            float a2 = Pa.z + S1.x + q2;
            float a3 = Pa.w + S1.y + q3;

            float p = fmaf(silu_f(a0), wq.x,
                      fmaf(silu_f(a1), wq.y,
                      fmaf(silu_f(a2), wq.z, silu_f(a3) * wq.w)));
            p += __shfl_xor_sync(0xffffffffu, p, 8);
            p += __shfl_xor_sync(0xffffffffu, p, 4);
            p += __shfl_xor_sync(0xffffffffu, p, 2);
            p += __shfl_xor_sync(0xffffffffu, p, 1);
            float att = 1.0f / (1.0f + __expf(-(p + ba2v)));

            red_add_v4(reinterpret_cast<float*>(outSBase + dstOff + lA),
                       att * S0.z * f0, att * S0.w * f1,
                       att * S1.z * f2c, att * S1.w * f3);

            if (l < 12) {
                float4 vv = __ldcg(reinterpret_cast<const float4*>(srBase + srcOff + 512u + lA));
                uint2 C0 = *reinterpret_cast<const uint2*>(tabBase + rowOff + 512u + 8u * v0);
                uint2 C1 = *reinterpret_cast<const uint2*>(tabBase + rowOff + 512u + 8u * v1);
                float2 c0a = __half22float2(*reinterpret_cast<const __half2*>(&C0.x));
                float2 c0b = __half22float2(*reinterpret_cast<const __half2*>(&C0.y));
                float2 c1a = __half22float2(*reinterpret_cast<const __half2*>(&C1.x));
                float2 c1b = __half22float2(*reinterpret_cast<const __half2*>(&C1.y));
                float fv0_ = fmaf(w, c0a.y, c0a.x);
                float fg0_ = fmaf(w, c0b.y, c0b.x);
                float fv1_ = fmaf(w, c1a.y, c1a.x);
                float fg1_ = fmaf(w, c1b.y, c1b.x);

                float vfa = fv0_;
                float vga = fg0_;
                float vfb = sk1 ? fv1_ : fv0_;
                float vgb = sk1 ? fg1_ : fg0_;
                float vfc = sk2 ? fv1_ : fv0_;
                float vgc = sk2 ? fg1_ : fg0_;
                float vfd = sk3 ? fv1_ : fv0_;
                float vgd = sk3 ? fg1_ : fg0_;

                float sha = (cmp0 == 0) ? uy : ((cmp0 == 1) ? uz : ux);
                float shb = (cmp1 == 0) ? uy : ((cmp1 == 1) ? uz : ux);
                float shcx = (cmp2 == 0) ? uy : ((cmp2 == 1) ? uz : ux);
                float shd = (cmp3 == 0) ? uy : ((cmp3 == 1) ? uz : ux);

                float m0 = att * fmaf(vv.x, vfa, vga * sha);
                float m1 = att * fmaf(vv.y, vfb, vgb * shb);
                float m2 = att * fmaf(vv.z, vfc, vgc * shcx);
                float m3 = att * fmaf(vv.w, vfd, vgd * shd);
                red_add_v4(reinterpret_cast<float*>(outVBase + vdOff + lA),
                           m0, m1, m2, m3);
            }
        }
    }
}

// ---------------------------------------------------------------------------
// Fork-join launch: init(s0) || tablepack(s1) || proj(s2), then edge(s0).
// ---------------------------------------------------------------------------
static cudaStream_t g_s1 = nullptr, g_s2 = nullptr;
static cudaEvent_t g_evRoot = nullptr, g_ev1 = nullptr, g_ev2 = nullptr;

extern "C" void kernel_launch(void* const* d_in, const int* in_sizes, int n_in,
                              void* d_out, int out_size) {
    const float* scalars = (const float*)d_in[0];
    const float* vectors = (const float*)d_in[1];
    const float* edge_vec = (const float*)d_in[2];
    const float* W1 = (const float*)d_in[3];
    const float* b1 = (const float*)d_in[4];
    const float* W2 = (const float*)d_in[5];
    const float* b2 = (const float*)d_in[6];
    const float* Wa1 = (const float*)d_in[7];
    const float* ba1 = (const float*)d_in[8];
    const float* Wa2 = (const float*)d_in[9];
    const float* ba2 = (const float*)d_in[10];
    const int* ei = (const int*)d_in[11];
    float* out = (float*)d_out;

    if (g_s1 == nullptr) {
        cudaStreamCreateWithFlags(&g_s1, cudaStreamNonBlocking);
        cudaStreamCreateWithFlags(&g_s2, cudaStreamNonBlocking);
        cudaEventCreateWithFlags(&g_evRoot, cudaEventDisableTiming);
        cudaEventCreateWithFlags(&g_ev1, cudaEventDisableTiming);
        cudaEventCreateWithFlags(&g_ev2, cudaEventDisableTiming);
    }

    // fork
    cudaEventRecord(g_evRoot, 0);
    cudaStreamWaitEvent(g_s1, g_evRoot, 0);
    cudaStreamWaitEvent(g_s2, g_evRoot, 0);

    const int TOT4 = (N_NODES * S_DIM + N_NODES * V_DIM * 3) / 4;
    init_out_kernel<<<(TOT4 + 255) / 256, 256>>>(scalars, vectors, out);
    tablepack_kernel<<<PK_ROWS, 320, 0, g_s1>>>(W1, b1, W2, b2, Wa1);
    proj_kernel<<<N_NODES / PROJ_NB, 256, 0, g_s2>>>(scalars, vectors, Wa1, ba1);

    // join
    cudaEventRecord(g_ev1, g_s1);
    cudaEventRecord(g_ev2, g_s2);
    cudaStreamWaitEvent(0, g_ev1, 0);
    cudaStreamWaitEvent(0, g_ev2, 0);

    edge_kernel<<<2500, 256>>>(edge_vec, ei, Wa2, ba2, out);
}

// round 17
// speedup vs baseline: 1.1092x; 1.0420x over previous
#include <cuda_runtime.h>
#include <cuda_bf16.h>
#include <cuda_fp16.h>
#include <math.h>

#define N_NODES 40000
#define E_EDGES 1280000
#define S_DIM 64
#define V_DIM 16
#define R_DIM 32

#define TBINS 4096
#define PK_ROWS 4097
#define PK_COLS 320          // halfs per row -> 640 bytes/row

#define SRROW 176            // g_SrcRow floats per node (704 B)

// Per-node data
__device__ __align__(16) float g_Pa[N_NODES * S_DIM];
__device__ __align__(16) float g_SrcRow[N_NODES * SRROW];  // [Pb|scalars interleaved | vectors(48)]
// Distance table (packed fp16 val/slope)
__device__ __align__(16) __half g_tabh[PK_ROWS * PK_COLS];

__device__ __forceinline__ float silu_f(float x) {
    return x / (1.0f + __expf(-x));
}
__device__ __forceinline__ void red_add_v4(float* ptr, float a, float b, float c, float d) {
    asm volatile("red.global.v4.f32.add [%0], {%1, %2, %3, %4};"
                 :: "l"(ptr), "f"(a), "f"(b), "f"(c), "f"(d) : "memory");
}

// ---------------------------------------------------------------------------
__global__ void init_out_kernel(const float* __restrict__ scalars,
                                const float* __restrict__ vectors,
                                float* __restrict__ out) {
    const int NS4 = (N_NODES * S_DIM) / 4;
    const int NV4 = (N_NODES * V_DIM * 3) / 4;
    int i = blockIdx.x * blockDim.x + threadIdx.x;
    if (i < NS4) {
        reinterpret_cast<float4*>(out)[i] =
            reinterpret_cast<const float4*>(scalars)[i];
    } else if (i < NS4 + NV4) {
        reinterpret_cast<float4*>(out)[i] =
            reinterpret_cast<const float4*>(vectors)[i - NS4];
    }
}

// ---------------------------------------------------------------------------
// proj: 2 cols x 4 nodes per thread.
// sWi[k*128 + jp*4 + {0..3}] = {Wa1[k*64+2jp], Wa1[k*64+2jp+1],
//                               Wa1[(64+k)*64+2jp], Wa1[(64+k)*64+2jp+1]}
// ---------------------------------------------------------------------------
#define PROJ_NB 32
__global__ __launch_bounds__(256) void proj_kernel(
    const float* __restrict__ scalars,
    const float* __restrict__ vectors,
    const float* __restrict__ Wa1,
    const float* __restrict__ ba1) {
    __shared__ __align__(16) float sWi[64 * 128];          // 32 KB
    __shared__ __align__(16) float sS[PROJ_NB * 64];       // 8 KB

    const int tid = threadIdx.x;
    const int n0 = blockIdx.x * PROJ_NB;

    for (int idx = tid; idx < 64 * 128; idx += 256) {
        int k = idx >> 7, r = idx & 127, jp = r >> 2, q = r & 3;
        sWi[idx] = Wa1[((q >= 2 ? 64 : 0) + k) * 64 + 2 * jp + (q & 1)];
    }
    for (int i = tid; i < PROJ_NB * 64; i += 256) sS[i] = scalars[n0 * 64 + i];
    __syncthreads();

    const int jp = tid & 31;           // column pair: j = 2jp, 2jp+1
    const int grp = tid >> 5;          // 0..7 -> nodes grp*4 .. grp*4+3
    const float* sbase = &sS[grp * 4 * 64];

    float pa0[4], pa1[4], pb0[4], pb1[4];
    {
        float2 b = *reinterpret_cast<const float2*>(&ba1[2 * jp]);
#pragma unroll
        for (int nn = 0; nn < 4; nn++) {
            pa0[nn] = b.x; pa1[nn] = b.y; pb0[nn] = 0.0f; pb1[nn] = 0.0f;
        }
    }

#pragma unroll 4
    for (int k = 0; k < 64; k++) {
        float4 wv = *reinterpret_cast<const float4*>(&sWi[k * 128 + jp * 4]);
#pragma unroll
        for (int nn = 0; nn < 4; nn++) {
            float s = sbase[nn * 64 + k];
            pa0[nn] = fmaf(s, wv.x, pa0[nn]);
            pa1[nn] = fmaf(s, wv.y, pa1[nn]);
            pb0[nn] = fmaf(s, wv.z, pb0[nn]);
            pb1[nn] = fmaf(s, wv.w, pb1[nn]);
        }
    }

#pragma unroll
    for (int nn = 0; nn < 4; nn++) {
        const int node = n0 + grp * 4 + nn;
        *reinterpret_cast<float2*>(&g_Pa[node * 64 + 2 * jp]) =
            make_float2(pa0[nn], pa1[nn]);
        *reinterpret_cast<float4*>(&g_SrcRow[node * SRROW + jp * 4]) =
            make_float4(pb0[nn], pb1[nn], sbase[nn * 64 + 2 * jp], sbase[nn * 64 + 2 * jp + 1]);
        if (jp < 24) {
            float2 vv = *reinterpret_cast<const float2*>(&vectors[node * 48 + 2 * jp]);
            *reinterpret_cast<float2*>(&g_SrcRow[node * SRROW + 128 + 2 * jp]) = vv;
        }
    }
}

// ---------------------------------------------------------------------------
// merged table+pack (unchanged)
// ---------------------------------------------------------------------------
__global__ __launch_bounds__(320) void tablepack_kernel(
    const float* __restrict__ W1, const float* __restrict__ b1,
    const float* __restrict__ W2, const float* __restrict__ b2,
    const float* __restrict__ Wa1) {
    __shared__ float rbf[2][32];
    __shared__ float hh[2][32];
    __shared__ float raw[2][160];

    const int t = threadIdx.x;
    const int hf = (t >= 160) ? 1 : 0;
    const int c = hf ? (t - 160) : t;
    const int row = blockIdx.x + hf;
    const float d = fminf((float)row, (float)TBINS) * (10.0f / TBINS);

    if (c < 32) {
        float freq01 = 0.1f * (float)(c + 1);
        float ds = fmaxf(d, 1e-8f);
        float bess;
        if (d < 1e-6f) bess = (float)M_PI * freq01;
        else           bess = sinpif(d * freq01) / ds;
        float cut = (d < 10.0f) ? 0.5f * (cospif(d * 0.1f) + 1.0f) : 0.0f;
        rbf[hf][c] = bess * cut;
    }
    __syncthreads();
    if (c < 32) {
        float acc = b1[c];
#pragma unroll 8
        for (int k = 0; k < 32; k++) acc = fmaf(rbf[hf][k], W1[k * 32 + c], acc);
        hh[hf][c] = silu_f(acc);
    }
    __syncthreads();

    float outv;
    if (c < 64) {
        float acc = b2[c];
#pragma unroll 8
        for (int jj = 0; jj < 32; jj++) acc = fmaf(hh[hf][jj], W2[jj * 96 + c], acc);
        outv = acc;
    } else if (c < 128) {
        int cc = c - 64;
        float acc = 0.0f;
#pragma unroll 8
        for (int k = 0; k < 32; k++) acc = fmaf(rbf[hf][k], Wa1[(128 + k) * 64 + cc], acc);
        outv = acc;
    } else {
        int cc = 64 + c - 128;
        float acc = b2[cc];
#pragma unroll 8
        for (int jj = 0; jj < 32; jj++) acc = fmaf(hh[hf][jj], W2[jj * 96 + cc], acc);
        outv = acc;
    }
    raw[hf][c] = outv;
    __syncthreads();

    const float* r0 = raw[0];
    const float* r1 = raw[1];
    float v;
    if (t < 128) {
        int g = t >> 3, k = t & 7;
        int col = 4 * g + (k & 3);
        v = (k < 4) ? r0[col] : (r1[col] - r0[col]);
    } else if (t < 256) {
        int u = t - 128;
        int g = u >> 3, k = u & 7;
        int col = 64 + 4 * g + (k & 3);
        v = (k < 4) ? r0[col] : (r1[col] - r0[col]);
    } else {
        int u = t - 256;
        int vg = u >> 2, k = u & 3;
        int col = 128 + vg + ((k >= 2) ? 16 : 0);
        v = ((k & 1) == 0) ? r0[col] : (r1[col] - r0[col]);
    }
    g_tabh[blockIdx.x * PK_COLS + t] = __float2half(v);
}

// ---------------------------------------------------------------------------
// edge kernel: R14 memory config; A/B table lerp in HFMA2.
// ---------------------------------------------------------------------------
__global__ __launch_bounds__(256) void edge_kernel(
    const float* __restrict__ edge_vec,
    const int* __restrict__ ei,
    const float* __restrict__ Wa2,
    const float* __restrict__ ba2,
    float* __restrict__ out) {

    __shared__ __align__(16) float sParam[8][32][8];   // 8 KB

    const int tid = threadIdx.x;
    const int warp = tid >> 5;
    const int lane = tid & 31;
    const int hw = lane >> 4;
    const int l = lane & 15;

    const float ba2v = __ldg(&ba2[0]);
    const float4 wq = *reinterpret_cast<const float4*>(Wa2 + 4 * l);

    const char* tabBase = (const char*)g_tabh;
    const char* paBase = (const char*)g_Pa;
    const char* srBase = (const char*)g_SrcRow;
    char* outSBase = (char*)out;
    char* outVBase = (char*)(out + N_NODES * S_DIM);

    const unsigned lA = (unsigned)l * 16u;

    const int e0i = 4 * l;
    const int v0 = e0i / 3;
    const int v1 = (e0i + 3) / 3;
    const int cmp0 = e0i % 3, cmp1 = (e0i + 1) % 3,
              cmp2 = (e0i + 2) % 3, cmp3 = (e0i + 3) % 3;
    const bool sk1 = ((e0i + 1) / 3) != v0;
    const bool sk2 = ((e0i + 2) / 3) != v0;
    const bool sk3 = ((e0i + 3) / 3) != v0;

    const int NWT = E_EDGES / 32;

    for (int wt = blockIdx.x * 8 + warp; wt < NWT; wt += gridDim.x * 8) {
        const int e = wt * 32 + lane;

        // ---- Phase A ----
        float x = __ldg(&edge_vec[3 * e + 0]);
        float y = __ldg(&edge_vec[3 * e + 1]);
        float z = __ldg(&edge_vec[3 * e + 2]);
        int sL = __ldg(&ei[e]);
        int dL = __ldg(&ei[E_EDGES + e]);
        float d = sqrtf(fmaf(x, x, fmaf(y, y, z * z)));
        float iv = 1.0f / fmaxf(d, 1e-8f);
        float dn = d * ((float)TBINS / 10.0f);
        int bin = min((int)dn, TBINS);

        __syncwarp();
        {
            float4 p0 = make_float4(dn - (float)bin, x * iv, y * iv, z * iv);
            float4 p1;
            p1.x = __uint_as_float((unsigned)bin * 640u);
            p1.y = __uint_as_float((unsigned)dL * 256u);
            p1.z = __uint_as_float((unsigned)sL * (SRROW * 4u));
            p1.w = 0.0f;
            *reinterpret_cast<float4*>(&sParam[warp][lane][0]) = p0;
            *reinterpret_cast<float4*>(&sParam[warp][lane][4]) = p1;
        }
        __syncwarp();

        // ---- Phase B: 16 iterations, 2 edges each ----
#pragma unroll 4
        for (int i = 0; i < 16; i++) {
            const int et = 2 * i + hw;
            float4 P0 = *reinterpret_cast<const float4*>(&sParam[warp][et][0]);
            float4 P1 = *reinterpret_cast<const float4*>(&sParam[warp][et][4]);
            float w = P0.x, ux = P0.y, uy = P0.z, uz = P0.w;
            unsigned rowOff = __float_as_uint(P1.x);
            unsigned dstOff = __float_as_uint(P1.y);
            unsigned srcOff = __float_as_uint(P1.z);
            unsigned vdOff = dstOff - (dstOff >> 2);   // dL*192

            uint4 Araw = *reinterpret_cast<const uint4*>(tabBase + rowOff + lA);
            uint4 Braw = *reinterpret_cast<const uint4*>(tabBase + rowOff + 256u + lA);
            float4 Pa = *reinterpret_cast<const float4*>(paBase + dstOff + lA);
            float4 S0 = *reinterpret_cast<const float4*>(srBase + srcOff + l * 32u);
            float4 S1 = *reinterpret_cast<const float4*>(srBase + srcOff + l * 32u + 16u);

            // fp16 lerp: f = val + w*slope (HFMA2), then one cvt per pair
            __half2 wh = __floats2half2_rn(w, w);
            float2 A01 = __half22float2(__hfma2(wh,
                            *reinterpret_cast<const __half2*>(&Araw.z),
                            *reinterpret_cast<const __half2*>(&Araw.x)));
            float2 A23 = __half22float2(__hfma2(wh,
                            *reinterpret_cast<const __half2*>(&Araw.w),
                            *reinterpret_cast<const __half2*>(&Araw.y)));
            float2 B01 = __half22float2(__hfma2(wh,
                            *reinterpret_cast<const __half2*>(&Braw.z),
                            *reinterpret_cast<const __half2*>(&Braw.x)));
            float2 B23 = __half22float2(__hfma2(wh,
                            *reinterpret_cast<const __half2*>(&Braw.w),
                            *reinterpret_cast<const __half2*>(&Braw.y)));

            float a0 = Pa.x + S0.x + B01.x;
            float a1 = Pa.y + S0.y + B01.y;
            float a2 = Pa.z + S1.x + B23.x;
            float a3 = Pa.w + S1.y + B23.y;

            float p = fmaf(silu_f(a0), wq.x,
                      fmaf(silu_f(a1), wq.y,
                      fmaf(silu_f(a2), wq.z, silu_f(a3) * wq.w)));
            p += __shfl_xor_sync(0xffffffffu, p, 8);
            p += __shfl_xor_sync(0xffffffffu, p, 4);
            p += __shfl_xor_sync(0xffffffffu, p, 2);
            p += __shfl_xor_sync(0xffffffffu, p, 1);
            float att = 1.0f / (1.0f + __expf(-(p + ba2v)));

            red_add_v4(reinterpret_cast<float*>(outSBase + dstOff + lA),
                       att * S0.z * A01.x, att * S0.w * A01.y,
                       att * S1.z * A23.x, att * S1.w * A23.y);

            if (l < 12) {
                float4 vv = *reinterpret_cast<const float4*>(srBase + srcOff + 512u + lA);
                uint2 C0 = *reinterpret_cast<const uint2*>(tabBase + rowOff + 512u + 8u * v0);
                uint2 C1 = *reinterpret_cast<const uint2*>(tabBase + rowOff + 512u + 8u * v1);
                float2 c0a = __half22float2(*reinterpret_cast<const __half2*>(&C0.x));
                float2 c0b = __half22float2(*reinterpret_cast<const __half2*>(&C0.y));
                float2 c1a = __half22float2(*reinterpret_cast<const __half2*>(&C1.x));
                float2 c1b = __half22float2(*reinterpret_cast<const __half2*>(&C1.y));
                float fv0_ = fmaf(w, c0a.y, c0a.x);
                float fg0_ = fmaf(w, c0b.y, c0b.x);
                float fv1_ = fmaf(w, c1a.y, c1a.x);
                float fg1_ = fmaf(w, c1b.y, c1b.x);

                float vfa = fv0_;
                float vga = fg0_;
                float vfb = sk1 ? fv1_ : fv0_;
                float vgb = sk1 ? fg1_ : fg0_;
                float vfc = sk2 ? fv1_ : fv0_;
                float vgc = sk2 ? fg1_ : fg0_;
                float vfd = sk3 ? fv1_ : fv0_;
                float vgd = sk3 ? fg1_ : fg0_;

                float sha = (cmp0 == 0) ? uy : ((cmp0 == 1) ? uz : ux);
                float shb = (cmp1 == 0) ? uy : ((cmp1 == 1) ? uz : ux);
                float shcx = (cmp2 == 0) ? uy : ((cmp2 == 1) ? uz : ux);
                float shd = (cmp3 == 0) ? uy : ((cmp3 == 1) ? uz : ux);

                float m0 = att * fmaf(vv.x, vfa, vga * sha);
                float m1 = att * fmaf(vv.y, vfb, vgb * shb);
                float m2 = att * fmaf(vv.z, vfc, vgc * shcx);
                float m3 = att * fmaf(vv.w, vfd, vgd * shd);
                red_add_v4(reinterpret_cast<float*>(outVBase + vdOff + lA),
                           m0, m1, m2, m3);
            }
        }
    }
}

// ---------------------------------------------------------------------------
// Fork-join launch: init(s0) || tablepack(s1) || proj(s2), then edge(s0).
// ---------------------------------------------------------------------------
static cudaStream_t g_s1 = nullptr, g_s2 = nullptr;
static cudaEvent_t g_evRoot = nullptr, g_ev1 = nullptr, g_ev2 = nullptr;

extern "C" void kernel_launch(void* const* d_in, const int* in_sizes, int n_in,
                              void* d_out, int out_size) {
    const float* scalars = (const float*)d_in[0];
    const float* vectors = (const float*)d_in[1];
    const float* edge_vec = (const float*)d_in[2];
    const float* W1 = (const float*)d_in[3];
    const float* b1 = (const float*)d_in[4];
    const float* W2 = (const float*)d_in[5];
    const float* b2 = (const float*)d_in[6];
    const float* Wa1 = (const float*)d_in[7];
    const float* ba1 = (const float*)d_in[8];
    const float* Wa2 = (const float*)d_in[9];
    const float* ba2 = (const float*)d_in[10];
    const int* ei = (const int*)d_in[11];
    float* out = (float*)d_out;

    if (g_s1 == nullptr) {
        cudaStreamCreateWithFlags(&g_s1, cudaStreamNonBlocking);
        cudaStreamCreateWithFlags(&g_s2, cudaStreamNonBlocking);
        cudaEventCreateWithFlags(&g_evRoot, cudaEventDisableTiming);
        cudaEventCreateWithFlags(&g_ev1, cudaEventDisableTiming);
        cudaEventCreateWithFlags(&g_ev2, cudaEventDisableTiming);
    }

    // fork
    cudaEventRecord(g_evRoot, 0);
    cudaStreamWaitEvent(g_s1, g_evRoot, 0);
    cudaStreamWaitEvent(g_s2, g_evRoot, 0);

    const int TOT4 = (N_NODES * S_DIM + N_NODES * V_DIM * 3) / 4;
    init_out_kernel<<<(TOT4 + 255) / 256, 256>>>(scalars, vectors, out);
    tablepack_kernel<<<PK_ROWS, 320, 0, g_s1>>>(W1, b1, W2, b2, Wa1);
    proj_kernel<<<N_NODES / PROJ_NB, 256, 0, g_s2>>>(scalars, vectors, Wa1, ba1);

    // join
    cudaEventRecord(g_ev1, g_s1);
    cudaEventRecord(g_ev2, g_s2);
    cudaStreamWaitEvent(0, g_ev1, 0);
    cudaStreamWaitEvent(0, g_ev2, 0);

    edge_kernel<<<2500, 256>>>(edge_vec, ei, Wa2, ba2, out);
}